// round 10
// baseline (speedup 1.0000x reference)
#include <cuda_runtime.h>
#include <math.h>
#include <stdint.h>

#define S_TOK 32
#define H_DIM 768
#define I_DIM 768
#define E_NUM 32
#define K_TOP 4
#define TWO_I 1536
#define LIMIT 7.0f
#define ALPHA 1.702f
#define EPS 1e-5f
#define TMAX 8

#define TR 32                 // weight rows per stage
#define ROW_PAD 772           // padded float stride (conflict-free: 772%32==4)
#define ROW_BYTES 3072        // 768 * 4
#define DSMEM_FLOATS (2 * TR * ROW_PAD + TMAX * ROW_PAD)
#define DSMEM_BYTES  (DSMEM_FLOATS * 4)   // 222,336

// -------- device scratch --------
__device__ float g_t[S_TOK][H_DIM];
__device__ int   g_topk_idx[S_TOK][K_TOP];
__device__ float g_topk_w[S_TOK][K_TOP];
__device__ float g_act[E_NUM][S_TOK][I_DIM];

// -------- PTX helpers --------
__device__ __forceinline__ uint32_t smem_u32(const void* p) {
    return (uint32_t)__cvta_generic_to_shared(p);
}
__device__ __forceinline__ void mbar_init(uint32_t a, uint32_t c) {
    asm volatile("mbarrier.init.shared.b64 [%0], %1;" :: "r"(a), "r"(c) : "memory");
}
__device__ __forceinline__ void mbar_expect(uint32_t a, uint32_t bytes) {
    asm volatile("mbarrier.arrive.expect_tx.shared.b64 _, [%0], %1;"
                 :: "r"(a), "r"(bytes) : "memory");
}
__device__ __forceinline__ void bulk_g2s(uint32_t dst, const void* src,
                                         uint32_t bytes, uint32_t mbar) {
    asm volatile(
        "cp.async.bulk.shared::cluster.global.mbarrier::complete_tx::bytes "
        "[%0], [%1], %2, [%3];"
        :: "r"(dst), "l"(src), "r"(bytes), "r"(mbar) : "memory");
}
__device__ __forceinline__ void mbar_wait(uint32_t mbar, uint32_t phase) {
    asm volatile(
        "{\n\t"
        ".reg .pred P;\n\t"
        "WAIT_%=:\n\t"
        "mbarrier.try_wait.parity.acquire.cta.shared::cta.b64 P, [%0], %1, 0x989680;\n\t"
        "@P bra DONE_%=;\n\t"
        "bra WAIT_%=;\n\t"
        "DONE_%=:\n\t"
        "}"
        :: "r"(mbar), "r"(phase) : "memory");
}

// ======================================================================
// Kernel 1: RMSNorm + residual init + router logits + top-4 + softmax
// ======================================================================
__global__ void __launch_bounds__(256) k_route(
    const float* __restrict__ x, const float* __restrict__ norm_scale,
    const float* __restrict__ gate_w, const float* __restrict__ gate_b,
    float* __restrict__ out)
{
    int s   = blockIdx.x;
    int tid = threadIdx.x;
    int lane = tid & 31, warp = tid >> 5;

    __shared__ float sh_t[H_DIM];
    __shared__ float sh_red[8];
    __shared__ float sh_g[E_NUM];

    float ss = 0.f;
    for (int c = tid; c < H_DIM; c += 256) {
        float v = x[s * H_DIM + c];
        sh_t[c] = v;
        out[s * H_DIM + c] = v;          // residual
        ss += v * v;
    }
    #pragma unroll
    for (int o = 16; o; o >>= 1) ss += __shfl_xor_sync(0xffffffffu, ss, o);
    if (lane == 0) sh_red[warp] = ss;
    __syncthreads();
    if (tid < 8) {
        float v = sh_red[tid];
        #pragma unroll
        for (int o = 4; o; o >>= 1) v += __shfl_xor_sync(0xffu, v, o);
        if (tid == 0) sh_red[0] = v;
    }
    __syncthreads();
    float rms = rsqrtf(sh_red[0] / (float)H_DIM + EPS);

    for (int c = tid; c < H_DIM; c += 256) {
        float tv = sh_t[c] * rms * norm_scale[c];
        sh_t[c] = tv;
        g_t[s][c] = tv;
    }
    __syncthreads();

    #pragma unroll
    for (int q = 0; q < 4; q++) {
        int e = warp * 4 + q;
        const float4* gwr = (const float4*)(gate_w + (size_t)e * H_DIM);
        float acc = 0.f;
        #pragma unroll
        for (int u = 0; u < 6; u++) {
            float4 w = gwr[lane + 32 * u];
            float4 t = *(const float4*)&sh_t[(lane + 32 * u) * 4];
            acc += w.x*t.x + w.y*t.y + w.z*t.z + w.w*t.w;
        }
        #pragma unroll
        for (int o = 16; o; o >>= 1) acc += __shfl_xor_sync(0xffffffffu, acc, o);
        if (lane == 0) sh_g[e] = acc + gate_b[e];
    }
    __syncthreads();

    if (tid == 0) {
        bool used[E_NUM];
        #pragma unroll
        for (int e = 0; e < E_NUM; e++) used[e] = false;
        float vals[K_TOP]; int idx[K_TOP];
        for (int k = 0; k < K_TOP; k++) {
            float best = -1e30f; int bi = 0;
            for (int e = 0; e < E_NUM; e++)
                if (!used[e] && sh_g[e] > best) { best = sh_g[e]; bi = e; }
            used[bi] = true; vals[k] = best; idx[k] = bi;
        }
        float m = vals[0], sum = 0.f, w[K_TOP];
        for (int k = 0; k < K_TOP; k++) { w[k] = __expf(vals[k] - m); sum += w[k]; }
        for (int k = 0; k < K_TOP; k++) {
            g_topk_idx[s][k] = idx[k];
            g_topk_w[s][k]   = w[k] / sum;
        }
    }
}

// ----------------------------------------------------------------------
// Per-block grouping: collect this expert's (token, weight) list.
// ----------------------------------------------------------------------
__device__ __forceinline__ int block_group(int e, int* sh_tok, float* sh_ew) {
    int c = 0;
    for (int s = 0; s < S_TOK; s++)
        #pragma unroll
        for (int k = 0; k < K_TOP; k++)
            if (g_topk_idx[s][k] == e) {
                sh_tok[c] = s; sh_ew[c] = g_topk_w[s][k]; c++;
            }
    return c;
}

// ======================================================================
// Kernel 2: w1 GEMV + SwiGLU. grid=(12,E), 256 thr.
// Block covers 128 rows = 4 TMA-staged buffers of TR=32 rows.
// Warp tile = 4 rows x 8 tokens; lane = 8*rr + j owns output[row][tok]
// fully in registers -> NO cross-lane reduction, 1 sync per stage.
// ======================================================================
__global__ void __launch_bounds__(256, 1) k_w1(
    const float* __restrict__ w1, const float* __restrict__ b1)
{
    extern __shared__ float dsm[];
    float* bufs = dsm;                           // 2 * TR * ROW_PAD
    float* sh_t = dsm + 2 * TR * ROW_PAD;        // TMAX * ROW_PAD

    __shared__ int   sh_tok[S_TOK];
    __shared__ float sh_ew[S_TOK];
    __shared__ int   sh_cnt;
    __shared__ uint64_t mbar_s[2];

    int e = blockIdx.y;
    int tid = threadIdx.x, lane = tid & 31, warp = tid >> 5;
    int rr = lane >> 3, j = lane & 7;            // row-in-warp, token

    if (tid == 0) {
        sh_cnt = block_group(e, sh_tok, sh_ew);
        mbar_init(smem_u32(&mbar_s[0]), 1);
        mbar_init(smem_u32(&mbar_s[1]), 1);
    }
    __syncthreads();
    int cnt = sh_cnt;
    if (cnt == 0) return;

    int rowbase = blockIdx.x * 128;
    const float* w1e = w1 + (size_t)e * TWO_I * H_DIM;
    const float* b1e = b1 + (size_t)e * TWO_I;
    uint32_t mb[2] = { smem_u32(&mbar_s[0]), smem_u32(&mbar_s[1]) };
    uint32_t ph[2] = { 0, 0 };
    uint32_t ba[2] = { smem_u32(bufs), smem_u32(bufs + TR * ROW_PAD) };

    for (int p0 = 0; p0 < cnt; p0 += TMAX) {
        int np = min(TMAX, cnt - p0);
        __syncthreads();
        for (int idx = tid; idx < TMAX * H_DIM; idx += 256) {
            int t = idx / H_DIM, c = idx - t * H_DIM;
            sh_t[t * ROW_PAD + c] = (t < np) ? g_t[sh_tok[p0 + t]][c] : 0.f;
        }
        __syncthreads();

        // prologue: stage 0 -> buf 0
        if (tid == 0) {
            mbar_expect(mb[0], TR * ROW_BYTES);
            for (int r = 0; r < TR; r++)
                bulk_g2s(ba[0] + r * (ROW_PAD * 4),
                         w1e + (size_t)(rowbase + r) * H_DIM, ROW_BYTES, mb[0]);
        }

        for (int s = 0; s < 4; s++) {
            int b = s & 1;
            if (s + 1 < 4 && tid == 0) {          // prefetch next stage
                int nb = b ^ 1;
                mbar_expect(mb[nb], TR * ROW_BYTES);
                for (int r = 0; r < TR; r++)
                    bulk_g2s(ba[nb] + r * (ROW_PAD * 4),
                             w1e + (size_t)(rowbase + (s + 1) * TR + r) * H_DIM,
                             ROW_BYTES, mb[nb]);
            }
            mbar_wait(mb[b], ph[b]); ph[b] ^= 1;

            int glob_r0 = rowbase + s * TR;
            int r_loc = 4 * warp + rr;
            const float4* wp = (const float4*)(bufs + (size_t)b * TR * ROW_PAD
                                               + (size_t)r_loc * ROW_PAD);
            const float4* tp = (const float4*)(sh_t + (size_t)j * ROW_PAD);

            float4 acc = make_float4(0.f, 0.f, 0.f, 0.f);
            #pragma unroll 8
            for (int c = 0; c < H_DIM / 4; c++) {
                float4 w = wp[c];
                float4 t = tp[c];
                acc.x += w.x * t.x; acc.y += w.y * t.y;
                acc.z += w.z * t.z; acc.w += w.w * t.w;
            }
            float h = (acc.x + acc.y) + (acc.z + acc.w) + b1e[glob_r0 + r_loc];

            // pair glu (even rr) with lin (odd rr): partner = lane ^ 8
            float hp = __shfl_xor_sync(0xffffffffu, h, 8);
            if ((rr & 1) == 0 && j < np) {
                float hg = fminf(h, LIMIT);
                float hl = fminf(fmaxf(hp, -LIMIT), LIMIT);
                float sg = 1.f / (1.f + __expf(-ALPHA * hg));
                int pr = (glob_r0 >> 1) + 2 * warp + (rr >> 1);
                g_act[e][p0 + j][pr] = hg * sg * (hl + 1.f);
            }
            __syncthreads();   // all warps done with buffer b before reuse
        }
    }
}

// ======================================================================
// Kernel 3: w2 GEMV + weighted atomic accumulate. grid=(12,E), 256 thr.
// Block covers 64 rows = 2 stages of TR=32. Same register-tile scheme.
// ======================================================================
__global__ void __launch_bounds__(256, 1) k_w2(
    const float* __restrict__ w2, const float* __restrict__ b2,
    float* __restrict__ out)
{
    extern __shared__ float dsm[];
    float* bufs = dsm;
    float* sh_a = dsm + 2 * TR * ROW_PAD;

    __shared__ int   sh_tok[S_TOK];
    __shared__ float sh_ew[S_TOK];
    __shared__ int   sh_cnt;
    __shared__ uint64_t mbar_s[2];

    int e = blockIdx.y;
    int tid = threadIdx.x, lane = tid & 31, warp = tid >> 5;
    int rr = lane >> 3, j = lane & 7;

    if (tid == 0) {
        sh_cnt = block_group(e, sh_tok, sh_ew);
        mbar_init(smem_u32(&mbar_s[0]), 1);
        mbar_init(smem_u32(&mbar_s[1]), 1);
    }
    __syncthreads();
    int cnt = sh_cnt;
    if (cnt == 0) return;

    int rowbase = blockIdx.x * 64;
    const float* w2e = w2 + (size_t)e * H_DIM * I_DIM;
    const float* b2e = b2 + (size_t)e * H_DIM;
    uint32_t mb[2] = { smem_u32(&mbar_s[0]), smem_u32(&mbar_s[1]) };
    uint32_t ph[2] = { 0, 0 };
    uint32_t ba[2] = { smem_u32(bufs), smem_u32(bufs + TR * ROW_PAD) };

    for (int p0 = 0; p0 < cnt; p0 += TMAX) {
        int np = min(TMAX, cnt - p0);
        __syncthreads();
        for (int idx = tid; idx < TMAX * I_DIM; idx += 256) {
            int t = idx / I_DIM, c = idx - t * I_DIM;
            sh_a[t * ROW_PAD + c] = (t < np) ? g_act[e][p0 + t][c] : 0.f;
        }
        __syncthreads();

        if (tid == 0) {
            mbar_expect(mb[0], TR * ROW_BYTES);
            for (int r = 0; r < TR; r++)
                bulk_g2s(ba[0] + r * (ROW_PAD * 4),
                         w2e + (size_t)(rowbase + r) * I_DIM, ROW_BYTES, mb[0]);
        }

        for (int s = 0; s < 2; s++) {
            int b = s & 1;
            if (s + 1 < 2 && tid == 0) {
                mbar_expect(mb[1], TR * ROW_BYTES);
                for (int r = 0; r < TR; r++)
                    bulk_g2s(ba[1] + r * (ROW_PAD * 4),
                             w2e + (size_t)(rowbase + TR + r) * I_DIM,
                             ROW_BYTES, mb[1]);
            }
            mbar_wait(mb[b], ph[b]); ph[b] ^= 1;

            int glob_r0 = rowbase + s * TR;
            int r_loc = 4 * warp + rr;
            const float4* wp = (const float4*)(bufs + (size_t)b * TR * ROW_PAD
                                               + (size_t)r_loc * ROW_PAD);
            const float4* tp = (const float4*)(sh_a + (size_t)j * ROW_PAD);

            float4 acc = make_float4(0.f, 0.f, 0.f, 0.f);
            #pragma unroll 8
            for (int c = 0; c < I_DIM / 4; c++) {
                float4 w = wp[c];
                float4 t = tp[c];
                acc.x += w.x * t.x; acc.y += w.y * t.y;
                acc.z += w.z * t.z; acc.w += w.w * t.w;
            }
            if (j < np) {
                float h = (acc.x + acc.y) + (acc.z + acc.w) + b2e[glob_r0 + r_loc];
                int tok = sh_tok[p0 + j];
                atomicAdd(&out[(size_t)tok * H_DIM + glob_r0 + r_loc],
                          h * sh_ew[p0 + j]);
            }
            __syncthreads();
        }
    }
}

// ======================================================================
extern "C" void kernel_launch(void* const* d_in, const int* in_sizes, int n_in,
                              void* d_out, int out_size)
{
    const float* x          = (const float*)d_in[0];
    const float* norm_scale = (const float*)d_in[1];
    const float* gate_w     = (const float*)d_in[2];
    const float* gate_b     = (const float*)d_in[3];
    const float* w1         = (const float*)d_in[4];
    const float* b1         = (const float*)d_in[5];
    const float* w2         = (const float*)d_in[6];
    const float* b2         = (const float*)d_in[7];
    float* out              = (float*)d_out;

    cudaFuncSetAttribute(k_w1, cudaFuncAttributeMaxDynamicSharedMemorySize, DSMEM_BYTES);
    cudaFuncSetAttribute(k_w2, cudaFuncAttributeMaxDynamicSharedMemorySize, DSMEM_BYTES);

    k_route<<<S_TOK, 256>>>(x, norm_scale, gate_w, gate_b, out);
    k_w1<<<dim3(12, E_NUM), 256, DSMEM_BYTES>>>(w1, b1);
    k_w2<<<dim3(12, E_NUM), 256, DSMEM_BYTES>>>(w2, b2, out);
}

// round 16
// speedup vs baseline: 1.8219x; 1.8219x over previous
#include <cuda_runtime.h>
#include <math.h>

#define S_TOK 32
#define H_DIM 768
#define I_DIM 768
#define E_NUM 32
#define K_TOP 4
#define TWO_I 1536
#define LIMIT 7.0f
#define ALPHA 1.702f
#define EPS 1e-5f
#define TMAX 8

// -------- device scratch --------
__device__ float g_t[S_TOK][H_DIM];
__device__ int   g_topk_idx[S_TOK][K_TOP];
__device__ float g_topk_w[S_TOK][K_TOP];
__device__ float g_act[E_NUM][S_TOK][I_DIM];

// ======================================================================
// Kernel 1: RMSNorm + residual init + router logits + top-4 + softmax.
// Top-4 warp-parallel (4 argmax rounds, deterministic tie-break).
// ======================================================================
__global__ void __launch_bounds__(256) k_route(
    const float* __restrict__ x, const float* __restrict__ norm_scale,
    const float* __restrict__ gate_w, const float* __restrict__ gate_b,
    float* __restrict__ out)
{
    int s   = blockIdx.x;
    int tid = threadIdx.x;
    int lane = tid & 31, warp = tid >> 5;

    __shared__ __align__(16) float sh_t[H_DIM];
    __shared__ float sh_red[8];
    __shared__ float sh_g[E_NUM];

    float ss = 0.f;
    for (int c = tid; c < H_DIM; c += 256) {
        float v = x[s * H_DIM + c];
        sh_t[c] = v;
        out[s * H_DIM + c] = v;          // residual
        ss += v * v;
    }
    #pragma unroll
    for (int o = 16; o; o >>= 1) ss += __shfl_xor_sync(0xffffffffu, ss, o);
    if (lane == 0) sh_red[warp] = ss;
    __syncthreads();
    if (tid < 8) {
        float v = sh_red[tid];
        #pragma unroll
        for (int o = 4; o; o >>= 1) v += __shfl_xor_sync(0xffu, v, o);
        if (tid == 0) sh_red[0] = v;
    }
    __syncthreads();
    float rms = rsqrtf(sh_red[0] / (float)H_DIM + EPS);

    for (int c = tid; c < H_DIM; c += 256) {
        float tv = sh_t[c] * rms * norm_scale[c];
        sh_t[c] = tv;
        g_t[s][c] = tv;
    }
    __syncthreads();

    // gate logits: warp q handles experts 4q..4q+3, vectorized
    #pragma unroll
    for (int q = 0; q < 4; q++) {
        int e = warp * 4 + q;
        const float4* gwr = (const float4*)(gate_w + (size_t)e * H_DIM);
        float acc = 0.f;
        #pragma unroll
        for (int u = 0; u < 6; u++) {
            float4 w = gwr[lane + 32 * u];
            float4 t = *(const float4*)&sh_t[(lane + 32 * u) * 4];
            acc += w.x*t.x + w.y*t.y + w.z*t.z + w.w*t.w;
        }
        #pragma unroll
        for (int o = 16; o; o >>= 1) acc += __shfl_xor_sync(0xffffffffu, acc, o);
        if (lane == 0) sh_g[e] = acc + gate_b[e];
    }
    __syncthreads();

    // warp-parallel top-4 (lane = expert), tie-break lowest index
    if (warp == 0) {
        float v = sh_g[lane];
        float vals[K_TOP]; int idxs[K_TOP];
        #pragma unroll
        for (int k = 0; k < K_TOP; k++) {
            float mv = v; int mi = lane;
            #pragma unroll
            for (int o = 16; o; o >>= 1) {
                float ov = __shfl_xor_sync(0xffffffffu, mv, o);
                int   oi = __shfl_xor_sync(0xffffffffu, mi, o);
                if (ov > mv || (ov == mv && oi < mi)) { mv = ov; mi = oi; }
            }
            vals[k] = mv; idxs[k] = mi;
            if (lane == mi) v = -1e30f;
        }
        if (lane == 0) {
            float m = vals[0], sum = 0.f, w[K_TOP];
            #pragma unroll
            for (int k = 0; k < K_TOP; k++) { w[k] = __expf(vals[k] - m); sum += w[k]; }
            #pragma unroll
            for (int k = 0; k < K_TOP; k++) {
                g_topk_idx[s][k] = idxs[k];
                g_topk_w[s][k]   = w[k] / sum;
            }
        }
    }
}

// ----------------------------------------------------------------------
// Warp-parallel, deterministic per-expert grouping (run by tid<32):
// slot(s) = popc(match_mask & lower_lanes) -> same order in k_w1 & k_w2.
// ----------------------------------------------------------------------
__device__ __forceinline__ void group_warp(int e, int tid,
                                           int* sh_tok, float* sh_ew, int* sh_cnt)
{
    if (tid < 32) {
        int s = tid;
        int my_k = -1;
        #pragma unroll
        for (int k = 0; k < K_TOP; k++)
            if (g_topk_idx[s][k] == e) my_k = k;
        unsigned mask = __ballot_sync(0xffffffffu, my_k >= 0);
        if (my_k >= 0) {
            int slot = __popc(mask & ((1u << s) - 1u));
            sh_tok[slot] = s;
            sh_ew[slot]  = g_topk_w[s][my_k];
        }
        if (s == 0) *sh_cnt = __popc(mask);
    }
}

// ----------------------------------------------------------------------
// R4 inner loop (best measured): dot of register-held weight row-pair
// against 4 SMEM tokens, warp reduce.
// ----------------------------------------------------------------------
__device__ __forceinline__ void pair_dot_reduce(
    const float4 wa[6], const float4 wb[6],
    const float (*sh)[H_DIM], int j0, int lane,
    float a0[4], float a1[4])
{
    #pragma unroll
    for (int j = 0; j < 4; j++) { a0[j] = 0.f; a1[j] = 0.f; }
    #pragma unroll
    for (int u = 0; u < 6; u++) {
        #pragma unroll
        for (int j = 0; j < 4; j++) {
            float4 tv = *(const float4*)&sh[j0 + j][(lane + 32 * u) * 4];
            a0[j] += wa[u].x*tv.x + wa[u].y*tv.y + wa[u].z*tv.z + wa[u].w*tv.w;
            a1[j] += wb[u].x*tv.x + wb[u].y*tv.y + wb[u].z*tv.z + wb[u].w*tv.w;
        }
    }
    #pragma unroll
    for (int j = 0; j < 4; j++) {
        #pragma unroll
        for (int o = 16; o; o >>= 1) {
            a0[j] += __shfl_xor_sync(0xffffffffu, a0[j], o);
            a1[j] += __shfl_xor_sync(0xffffffffu, a1[j], o);
        }
    }
}

// ======================================================================
// Kernel 2: w1 GEMV + SwiGLU. grid=(12, E, 2); z picks token pass
// (z=0: tokens 0..7, z=1: 8..15). Single pass per block -> short tail.
// ======================================================================
__global__ void __launch_bounds__(256) k_w1(
    const float* __restrict__ w1, const float* __restrict__ b1)
{
    __shared__ __align__(16) float sh_t[TMAX][H_DIM];
    __shared__ int   sh_tok[S_TOK];
    __shared__ float sh_ew[S_TOK];
    __shared__ int   sh_cnt;

    int e   = blockIdx.y;
    int tid = threadIdx.x, lane = tid & 31, warp = tid >> 5;

    group_warp(e, tid, sh_tok, sh_ew, &sh_cnt);
    __syncthreads();
    int cnt = sh_cnt;
    int p0  = blockIdx.z * TMAX;
    if (p0 >= cnt) return;
    int np  = min(TMAX, cnt - p0);
    int np4 = (np + 3) & ~3;

    for (int idx = tid; idx < np4 * H_DIM; idx += 256) {
        int j = idx / H_DIM, c = idx - j * H_DIM;
        sh_t[j][c] = (j < np) ? g_t[sh_tok[p0 + j]][c] : 0.f;
    }
    __syncthreads();

    int pairbase = blockIdx.x * 64;
    const float* w1e = w1 + (size_t)e * TWO_I * H_DIM;
    const float* b1e = b1 + (size_t)e * TWO_I;

    for (int p = warp; p < 64; p += 8) {
        int pr = pairbase + p;
        int r0 = 2 * pr;
        const float4* wr0 = (const float4*)(w1e + (size_t)r0 * H_DIM);
        const float4* wr1 = (const float4*)(w1e + (size_t)(r0 + 1) * H_DIM);

        float4 wa[6], wb[6];
        #pragma unroll
        for (int u = 0; u < 6; u++) {
            wa[u] = wr0[lane + 32 * u];
            wb[u] = wr1[lane + 32 * u];
        }
        float bg = b1e[r0], bl = b1e[r0 + 1];

        for (int j0 = 0; j0 < np4; j0 += 4) {
            float a0[4], a1[4];
            pair_dot_reduce(wa, wb, sh_t, j0, lane, a0, a1);
            #pragma unroll
            for (int j = 0; j < 4; j++) {
                if (lane == j && j0 + j < np) {
                    float hg = fminf(a0[j] + bg, LIMIT);
                    float hl = fminf(fmaxf(a1[j] + bl, -LIMIT), LIMIT);
                    float sg = 1.f / (1.f + __expf(-ALPHA * hg));
                    g_act[e][p0 + j0 + j][pr] = hg * sg * (hl + 1.f);
                }
            }
        }
    }
}

// ======================================================================
// Kernel 3: w2 GEMV + weighted atomic accumulate. grid=(12, E, 2).
// ======================================================================
__global__ void __launch_bounds__(256) k_w2(
    const float* __restrict__ w2, const float* __restrict__ b2,
    float* __restrict__ out)
{
    __shared__ __align__(16) float sh_a[TMAX][H_DIM];
    __shared__ int   sh_tok[S_TOK];
    __shared__ float sh_ew[S_TOK];
    __shared__ int   sh_cnt;

    int e   = blockIdx.y;
    int tid = threadIdx.x, lane = tid & 31, warp = tid >> 5;

    group_warp(e, tid, sh_tok, sh_ew, &sh_cnt);
    __syncthreads();
    int cnt = sh_cnt;
    int p0  = blockIdx.z * TMAX;
    if (p0 >= cnt) return;
    int np  = min(TMAX, cnt - p0);
    int np4 = (np + 3) & ~3;

    for (int idx = tid; idx < np4 * I_DIM; idx += 256) {
        int j = idx / I_DIM, c = idx - j * I_DIM;
        sh_a[j][c] = (j < np) ? g_act[e][p0 + j][c] : 0.f;
    }
    __syncthreads();

    int pairbase = blockIdx.x * 32;
    const float* w2e = w2 + (size_t)e * H_DIM * I_DIM;
    const float* b2e = b2 + (size_t)e * H_DIM;

    for (int p = warp; p < 32; p += 8) {
        int r0 = 2 * (pairbase + p);
        const float4* wr0 = (const float4*)(w2e + (size_t)r0 * I_DIM);
        const float4* wr1 = (const float4*)(w2e + (size_t)(r0 + 1) * I_DIM);

        float4 wa[6], wb[6];
        #pragma unroll
        for (int u = 0; u < 6; u++) {
            wa[u] = wr0[lane + 32 * u];
            wb[u] = wr1[lane + 32 * u];
        }
        float bb0 = b2e[r0], bb1 = b2e[r0 + 1];

        for (int j0 = 0; j0 < np4; j0 += 4) {
            float a0[4], a1[4];
            pair_dot_reduce(wa, wb, sh_a, j0, lane, a0, a1);
            #pragma unroll
            for (int j = 0; j < 4; j++) {
                if (lane == j && j0 + j < np) {
                    float ww = sh_ew[p0 + j0 + j];
                    int   tk = sh_tok[p0 + j0 + j];
                    atomicAdd(&out[(size_t)tk * H_DIM + r0],     (a0[j] + bb0) * ww);
                    atomicAdd(&out[(size_t)tk * H_DIM + r0 + 1], (a1[j] + bb1) * ww);
                }
            }
        }
    }
}

// ======================================================================
extern "C" void kernel_launch(void* const* d_in, const int* in_sizes, int n_in,
                              void* d_out, int out_size)
{
    const float* x          = (const float*)d_in[0];
    const float* norm_scale = (const float*)d_in[1];
    const float* gate_w     = (const float*)d_in[2];
    const float* gate_b     = (const float*)d_in[3];
    const float* w1         = (const float*)d_in[4];
    const float* b1         = (const float*)d_in[5];
    const float* w2         = (const float*)d_in[6];
    const float* b2         = (const float*)d_in[7];
    float* out              = (float*)d_out;

    k_route<<<S_TOK, 256>>>(x, norm_scale, gate_w, gate_b, out);
    k_w1<<<dim3(12, E_NUM, 2), 256>>>(w1, b1);
    k_w2<<<dim3(12, E_NUM, 2), 256>>>(w2, b2, out);
}